// round 16
// baseline (speedup 1.0000x reference)
#include <cuda_runtime.h>
#include <cuda_bf16.h>

// Problem constants
#define NS 5
#define ND 64
#define NV 1024
#define NH 961
#define HPITCH 1092
#define BPITCH 1088
#define MAXB 4096
#define CHUNK 2048
#define GT_BLOCKS 320      // NS*NV*ND/4/256
// Gemm SMEM: B(hi+lo) 36864 + X ping-pong 2*(9216+9216) = 73728
#define GEMM_SMEM 73728

// Precomputed once per launch:
__device__ float g_sp[NS][NV];
// Split-bf16 operands for the conv GEMM: GT[s][o][d] = hp[s][d + 1023 - o]
__device__ __align__(16) __nv_bfloat16 g_GThi[NS][NV][ND];
__device__ __align__(16) __nv_bfloat16 g_GTlo[NS][NV][ND];
__device__ __align__(16) __nv_bfloat16 g_Xhi[MAXB * NS * ND];
__device__ __align__(16) __nv_bfloat16 g_Xlo[MAXB * NS * ND];
__device__ float g_Y[(size_t)MAXB * NS * NV];   // silu(conv) -- pre-activated

__device__ __forceinline__ float silu_f(float y) {
    return y * (1.0f / (1.0f + __expf(-y)));
}
__device__ __forceinline__ float silu_t(float x) {        // tanh.approx, 1 MUFU
    const float h = 0.5f * x;
    float t;
    asm("tanh.approx.f32 %0, %1;" : "=f"(t) : "f"(h));
    return fmaf(h, t, h);
}
__device__ __forceinline__ float warp_sum(float v) {
#pragma unroll
    for (int o = 16; o; o >>= 1) v += __shfl_xor_sync(0xffffffffu, v, o);
    return v;
}
__device__ __forceinline__ void ffma2(unsigned long long& acc,
                                      unsigned long long x,
                                      unsigned long long g) {
    asm("fma.rn.f32x2 %0, %1, %2, %0;" : "+l"(acc) : "l"(x), "l"(g));
}
__device__ __forceinline__ unsigned long long add2(unsigned long long a,
                                                   unsigned long long b) {
    unsigned long long r;
    asm("add.rn.f32x2 %0, %1, %2;" : "=l"(r) : "l"(a), "l"(b));
    return r;
}
__device__ __forceinline__ unsigned long long mul2(unsigned long long a,
                                                   unsigned long long b) {
    unsigned long long r;
    asm("mul.rn.f32x2 %0, %1, %2;" : "=l"(r) : "l"(a), "l"(b));
    return r;
}
__device__ __forceinline__ unsigned long long packf2(float lo, float hi) {
    unsigned long long r;
    asm("mov.b64 %0, {%1, %2};" : "=l"(r) : "r"(__float_as_uint(lo)),
        "r"(__float_as_uint(hi)));
    return r;
}
__device__ __forceinline__ float u64lo(unsigned long long u) {
    return __uint_as_float((unsigned)u);
}
__device__ __forceinline__ float u64hi(unsigned long long u) {
    return __uint_as_float((unsigned)(u >> 32));
}

// m16n8k16 row.col bf16 MMA, fp32 accumulate (D == C).
__device__ __forceinline__ void mma16816(float* c, const unsigned* a,
                                         const unsigned* b) {
    asm volatile(
        "mma.sync.aligned.m16n8k16.row.col.f32.bf16.bf16.f32 "
        "{%0,%1,%2,%3}, {%4,%5,%6,%7}, {%8,%9}, {%0,%1,%2,%3};\n"
        : "+f"(c[0]), "+f"(c[1]), "+f"(c[2]), "+f"(c[3])
        : "r"(a[0]), "r"(a[1]), "r"(a[2]), "r"(a[3]), "r"(b[0]), "r"(b[1]));
}
__device__ __forceinline__ void ldsm4(unsigned* r, const void* p) {
    const unsigned addr = (unsigned)__cvta_generic_to_shared(p);
    asm volatile("ldmatrix.sync.aligned.m8n8.x4.shared.b16 {%0,%1,%2,%3}, [%4];"
                 : "=r"(r[0]), "=r"(r[1]), "=r"(r[2]), "=r"(r[3]) : "r"(addr));
}
__device__ __forceinline__ void cp16(void* dst, const void* src) {
    const unsigned d = (unsigned)__cvta_generic_to_shared(dst);
    asm volatile("cp.async.ca.shared.global [%0], [%1], 16;"
                 :: "r"(d), "l"(src));
}

// ---- fully packed scalar conv (sp branch only; exact fp32) ----
__device__ __forceinline__ void conv4p(const float* __restrict__ gA,
                                       const float* __restrict__ gB,
                                       const float* __restrict__ xs,
                                       float a[4]) {
    const ulonglong2* a2v = (const ulonglong2*)gA;
    const ulonglong2* b2v = (const ulonglong2*)gB;
    const ulonglong2* x2v = (const ulonglong2*)xs;
    unsigned long long A3 = 0ull, A2 = 0ull, A1 = 0ull, A0 = 0ull;
    ulonglong2 GA = a2v[0];
    ulonglong2 GB = b2v[0];
#pragma unroll
    for (int m = 0; m < 16; m++) {
        const ulonglong2 GAn = a2v[m + 1];
        const ulonglong2 GBn = b2v[m + 1];
        const ulonglong2 X = x2v[m];
        ffma2(A3, X.x, GA.x);
        ffma2(A1, X.x, GA.y);
        ffma2(A2, X.x, GB.x);
        ffma2(A0, X.x, GB.y);
        ffma2(A3, X.y, GA.y);
        ffma2(A1, X.y, GAn.x);
        ffma2(A2, X.y, GB.y);
        ffma2(A0, X.y, GBn.x);
        GA = GAn;
        GB = GBn;
    }
    a[3] = u64lo(A3) + u64hi(A3);
    a[2] = u64lo(A2) + u64hi(A2);
    a[1] = u64lo(A1) + u64hi(A1);
    a[0] = u64lo(A0) + u64hi(A0);
}

// --------------------------------------------------------------------------
// Kernel 1: merged prep (sp | GT build | x split), one launch.
// --------------------------------------------------------------------------
__global__ __launch_bounds__(256) void prep_kernel(
    const float* __restrict__ h, const float* __restrict__ symbols,
    const float* __restrict__ gamma, const float* __restrict__ beta,
    const float* __restrict__ values, int n) {
    const int bx = blockIdx.x;
    const int t = threadIdx.x;

    if (bx >= 5 + GT_BLOCKS) {               // ---- x split ----
        const int i = ((bx - 5 - GT_BLOCKS) * 256 + t) * 4;
        if (i < n) {
            const float4 v = *(const float4*)(values + i);
            __nv_bfloat16 h0 = __float2bfloat16(v.x);
            __nv_bfloat16 h1 = __float2bfloat16(v.y);
            __nv_bfloat16 h2 = __float2bfloat16(v.z);
            __nv_bfloat16 h3 = __float2bfloat16(v.w);
            __nv_bfloat162* ph = (__nv_bfloat162*)(&g_Xhi[i]);
            ph[0] = __nv_bfloat162(h0, h1);
            ph[1] = __nv_bfloat162(h2, h3);
            __nv_bfloat162* pl = (__nv_bfloat162*)(&g_Xlo[i]);
            pl[0] = __nv_bfloat162(__float2bfloat16(v.x - __bfloat162float(h0)),
                                   __float2bfloat16(v.y - __bfloat162float(h1)));
            pl[1] = __nv_bfloat162(__float2bfloat16(v.z - __bfloat162float(h2)),
                                   __float2bfloat16(v.w - __bfloat162float(h3)));
        }
        return;
    }
    if (bx >= 5) {                           // ---- GT build ----
        const int idx = (bx - 5) * 256 + t;
#pragma unroll
        for (int q = 0; q < 4; q++) {
            const int e = idx * 4 + q;
            const int s = e / (NV * ND);
            const int rem = e - s * (NV * ND);
            const int o = rem >> 6, d = rem & 63;
            const int j = d + 1023 - o;
            const float v = (j >= 63 && j < 63 + NH) ? h[s * NH + (j - 63)] : 0.f;
            const __nv_bfloat16 hi = __float2bfloat16(v);
            (&g_GThi[0][0][0])[e] = hi;
            (&g_GTlo[0][0][0])[e] = __float2bfloat16(v - __bfloat162float(hi));
        }
        return;
    }

    // ---- sp: conv-net on symbols, one block per s ----
    __shared__ __align__(16) float hpA[HPITCH];
    __shared__ __align__(16) float hpB[BPITCH];
    __shared__ __align__(16) float xs[ND];
    __shared__ float wsum[8], wsq[8], mu_rs[2];
    const int s = bx;
    const int warp = t >> 5, lane = t & 31;

    for (int i = t; i < HPITCH; i += 256)
        hpA[i] = (i >= 63 && i < 63 + NH) ? h[s * NH + (i - 63)] : 0.f;
    for (int i = t; i < BPITCH; i += 256) {
        const int j = i + 1;
        hpB[i] = (j >= 63 && j < 63 + NH) ? h[s * NH + (j - 63)] : 0.f;
    }
    if (t < ND) xs[t] = symbols[s * ND + t];
    __syncthreads();

    const int o0 = 4 * t;
    float a[4];
    conv4p(hpA + (1020 - o0), hpB + (1020 - o0), xs, a);

    float sm = 0.f, sq = 0.f;
#pragma unroll
    for (int k = 0; k < 4; k++) {
        a[k] = silu_f(a[k]);
        sm += a[k];
        sq += a[k] * a[k];
    }
    sm = warp_sum(sm);
    sq = warp_sum(sq);
    if (lane == 0) { wsum[warp] = sm; wsq[warp] = sq; }
    __syncthreads();
    if (t == 0) {
        float s1 = 0.f, s2 = 0.f;
#pragma unroll
        for (int w = 0; w < 8; w++) { s1 += wsum[w]; s2 += wsq[w]; }
        const float mu = s1 * (1.f / NV);
        mu_rs[0] = mu;
        mu_rs[1] = rsqrtf(s2 * (1.f / NV) - mu * mu + 1e-3f);
    }
    __syncthreads();
    const float mu = mu_rs[0], rstd = mu_rs[1];
#pragma unroll
    for (int k = 0; k < 4; k++) {
        const int o = o0 + k;
        g_sp[s][o] = (a[k] - mu) * rstd * gamma[o] + beta[o];
    }
}

// --------------------------------------------------------------------------
// Kernel 2: persistent conv GEMM + fused silu.
// Each CTA: stage B (GT tile, shared across all M) ONCE, then 2 M-tiles of
// 64 batches with ping-pong cp.async X buffers (X1 load hides under m0).
// CTA tile per step: M=64 x N=128 x K=64; 8 warps = 2m x 4n, warp tile 32x32.
// --------------------------------------------------------------------------
__global__ __launch_bounds__(256, 3) void gemm_kernel(int c0, int B) {
    extern __shared__ __align__(16) char dsm[];
    __nv_bfloat16 (*sBhi)[72] = (__nv_bfloat16(*)[72])(dsm);           // 128 rows
    __nv_bfloat16 (*sBlo)[72] = (__nv_bfloat16(*)[72])(dsm + 18432);   // 128 rows

    const int s = blockIdx.z;
    const int n0 = blockIdx.y * 128;
    const int bmb = c0 + blockIdx.x * 128;     // this CTA covers 128 batches
    const int t = threadIdx.x;

    const uint4* GThi4 = (const uint4*)(&g_GThi[s][0][0]);
    const uint4* GTlo4 = (const uint4*)(&g_GTlo[s][0][0]);
    const uint4* Xhi4 = (const uint4*)g_Xhi;
    const uint4* Xlo4 = (const uint4*)g_Xlo;

    // ---- stage B + X0 (group 0), then X1 (group 1) ----
#pragma unroll
    for (int u = 0; u < 4; u++) {
        const int idx = t + u * 256;
        const int row = idx >> 3, q = idx & 7;
        cp16(&sBhi[row][q * 8], &GThi4[(n0 + row) * 8 + q]);
        cp16(&sBlo[row][q * 8], &GTlo4[(n0 + row) * 8 + q]);
    }
#pragma unroll
    for (int m = 0; m < 2; m++) {
        __nv_bfloat16 (*sXhi)[72] =
            (__nv_bfloat16(*)[72])(dsm + 36864 + m * 18432);
        __nv_bfloat16 (*sXlo)[72] =
            (__nv_bfloat16(*)[72])(dsm + 36864 + m * 18432 + 9216);
        const int base = bmb + m * 64;
#pragma unroll
        for (int u = 0; u < 2; u++) {
            const int idx = t + u * 256;
            const int row = idx >> 3, q = idx & 7;
            const int r = min(base + row, B - 1);
            cp16(&sXhi[row][q * 8], &Xhi4[(r * NS + s) * 8 + q]);
            cp16(&sXlo[row][q * 8], &Xlo4[(r * NS + s) * 8 + q]);
        }
        asm volatile("cp.async.commit_group;");
    }

    const int warp = t >> 5, lane = t & 31;
    const int wm = warp & 1, wn = warp >> 1;     // wn in 0..3
    const int g = lane >> 2, t4 = lane & 3;
    const int arow_l = (lane & 15);
    const int acol_l = (lane >> 4) << 3;
    const int brow_l = ((lane >> 4) << 3) + (lane & 7);
    const int bcol_l = ((lane >> 3) & 1) << 3;

#pragma unroll
    for (int m = 0; m < 2; m++) {
        if (m == 0) asm volatile("cp.async.wait_group 1;");
        else        asm volatile("cp.async.wait_group 0;");
        __syncthreads();

        __nv_bfloat16 (*sXhi)[72] =
            (__nv_bfloat16(*)[72])(dsm + 36864 + m * 18432);
        __nv_bfloat16 (*sXlo)[72] =
            (__nv_bfloat16(*)[72])(dsm + 36864 + m * 18432 + 9216);
        const int bm0 = bmb + m * 64;

        float acc[2][4][4];
#pragma unroll
        for (int mi = 0; mi < 2; mi++)
#pragma unroll
            for (int j = 0; j < 4; j++)
#pragma unroll
                for (int c = 0; c < 4; c++) acc[mi][j][c] = 0.f;

#pragma unroll
        for (int ks = 0; ks < 4; ks++) {
            const int k0 = ks * 16;
            unsigned ahi[2][4], alo[2][4], bhi[2][4], blo[2][4];
#pragma unroll
            for (int mi = 0; mi < 2; mi++) {
                const int r = wm * 32 + mi * 16 + arow_l;
                ldsm4(ahi[mi], &sXhi[r][k0 + acol_l]);
                ldsm4(alo[mi], &sXlo[r][k0 + acol_l]);
            }
#pragma unroll
            for (int half = 0; half < 2; half++) {
                const int nr = wn * 32 + half * 16 + brow_l;
                ldsm4(bhi[half], &sBhi[nr][k0 + bcol_l]);
                ldsm4(blo[half], &sBlo[nr][k0 + bcol_l]);
            }
#pragma unroll
            for (int j = 0; j < 4; j++) {
                const int hf = j >> 1, sub = j & 1;
                const unsigned bh[2] = {bhi[hf][2 * sub], bhi[hf][2 * sub + 1]};
                const unsigned bl[2] = {blo[hf][2 * sub], blo[hf][2 * sub + 1]};
#pragma unroll
                for (int mi = 0; mi < 2; mi++) {
                    mma16816(acc[mi][j], ahi[mi], bh);
                    mma16816(acc[mi][j], ahi[mi], bl);
                    mma16816(acc[mi][j], alo[mi], bh);
                }
            }
        }

        // silu + store Y
#pragma unroll
        for (int mi = 0; mi < 2; mi++) {
            const int r0 = bm0 + wm * 32 + mi * 16 + g;
#pragma unroll
            for (int j = 0; j < 4; j++) {
                const int col = n0 + wn * 32 + j * 8 + 2 * t4;
                if (r0 < B)
                    *(float2*)(g_Y + ((size_t)r0 * NS + s) * NV + col) =
                        make_float2(silu_f(acc[mi][j][0]), silu_f(acc[mi][j][1]));
                if (r0 + 8 < B)
                    *(float2*)(g_Y + ((size_t)(r0 + 8) * NS + s) * NV + col) =
                        make_float2(silu_f(acc[mi][j][2]), silu_f(acc[mi][j][3]));
            }
        }
    }
}

// --------------------------------------------------------------------------
// Kernel 3: epilogue for one chunk. One CTA per batch. Y is pre-silu'd.
// --------------------------------------------------------------------------
__global__ __launch_bounds__(256, 4) void epi_kernel(
    const float* __restrict__ gamma, const float* __restrict__ beta,
    float* __restrict__ out, int c0) {
    __shared__ float wsum[NS][8], wsq[NS][8];
    __shared__ float mu_s[NS], rs_s[NS];
    __shared__ unsigned spartP[NS][2][8];
    __shared__ float score[25];
    __shared__ float prob[NS][NS];

    const int b = c0 + blockIdx.x;
    const int t = threadIdx.x;
    const int warp = t >> 5, lane = t & 31;

    float4 VPX[NS];
#pragma unroll
    for (int i = 0; i < NS; i++) {
        const float4 v = ((const float4*)(g_Y + ((size_t)b * NS + i) * NV))[t];
        VPX[i] = v;
        float sm = v.x + v.y + v.z + v.w;
        float sq = v.x * v.x + v.y * v.y + v.z * v.z + v.w * v.w;
        sm = warp_sum(sm);
        sq = warp_sum(sq);
        if (lane == 0) { wsum[i][warp] = sm; wsq[i][warp] = sq; }
    }
    __syncthreads();
    if (t < NS) {
        float s1 = 0.f, s2 = 0.f;
#pragma unroll
        for (int w = 0; w < 8; w++) { s1 += wsum[t][w]; s2 += wsq[t][w]; }
        const float mu = s1 * (1.f / NV);
        mu_s[t] = mu;
        rs_s[t] = rsqrtf(s2 * (1.f / NV) - mu * mu + 1e-3f);
    }
    __syncthreads();

    const float4 gm4 = ((const float4*)gamma)[t];
    const float4 bt4 = ((const float4*)beta)[t];
    unsigned long long VU[NS][2];
#pragma unroll
    for (int i = 0; i < NS; i++) {
        const float mu = mu_s[i], rs = rs_s[i];
        VU[i][0] = packf2((VPX[i].x - mu) * rs * gm4.x + bt4.x,
                          (VPX[i].y - mu) * rs * gm4.y + bt4.y);
        VU[i][1] = packf2((VPX[i].z - mu) * rs * gm4.z + bt4.z,
                          (VPX[i].w - mu) * rs * gm4.w + bt4.w);
    }

    unsigned long long SU[NS][2];
#pragma unroll
    for (int j = 0; j < NS; j++) {
        const float4 sp = ((const float4*)(&g_sp[j][0]))[t];
        SU[j][0] = packf2(sp.x, sp.y);
        SU[j][1] = packf2(sp.z, sp.w);
    }

#pragma unroll
    for (int j = 0; j < NS; j++) {
        unsigned p0 = 0, p1 = 0;
#pragma unroll
        for (int i = 0; i < NS; i++) {
            const unsigned long long x0 = VU[i][0] ^ add2(VU[i][0], SU[j][0]);
            const unsigned long long x1 = VU[i][1] ^ add2(VU[i][1], SU[j][1]);
            const unsigned a = (unsigned)((x0 >> 31) & 1u) + (unsigned)(x0 >> 63) +
                               (unsigned)((x1 >> 31) & 1u) + (unsigned)(x1 >> 63);
            if (i < 4) p0 += a << (8 * i); else p1 = a;
        }
        p0 = __reduce_add_sync(0xffffffffu, p0);
        p1 = __reduce_add_sync(0xffffffffu, p1);
        if (lane == 0) { spartP[j][0][warp] = p0; spartP[j][1][warp] = p1; }
    }
    __syncthreads();
    if (t < 25) {
        const int j = t / 5, i = t % 5;
        unsigned sm = 0;
#pragma unroll
        for (int w = 0; w < 8; w++)
            sm += (i < 4) ? ((spartP[j][0][w] >> (8 * i)) & 255u)
                          : (spartP[j][1][w] & 255u);
        score[t] = (float)(NV - 2 * (int)sm) * (1.f / NV);
    }
    __syncthreads();
    if (t < NS) {
        float sc[NS];
        float ssum = 0.f;
#pragma unroll
        for (int i = 0; i < NS; i++) {
            sc[i] = __expf(score[t * NS + i]);
            ssum += sc[i];
        }
        const float inv = 1.f / ssum;
#pragma unroll
        for (int i = 0; i < NS; i++) prob[t][i] = sc[i] * inv;
    }
    __syncthreads();

    float4* out4 = (float4*)(out + (size_t)b * (NS * NV));
#pragma unroll
    for (int j = 0; j < NS; j++) {
        unsigned long long at0 = 0ull, at1 = 0ull;
#pragma unroll
        for (int i = 0; i < NS; i++) {
            const float p = prob[j][i];
            const unsigned long long pp = packf2(p, p);
            ffma2(at0, pp, VU[i][0]);
            ffma2(at1, pp, VU[i][1]);
        }
        at0 = mul2(at0, SU[j][0]);
        at1 = mul2(at1, SU[j][1]);
        float4 w4;
        w4.x = silu_t(u64lo(at0));
        w4.y = silu_t(u64hi(at0));
        w4.z = silu_t(u64lo(at1));
        w4.w = silu_t(u64hi(at1));
        out4[j * 256 + t] = w4;
    }
}

extern "C" void kernel_launch(void* const* d_in, const int* in_sizes, int n_in,
                              void* d_out, int out_size) {
    const float* values  = (const float*)d_in[0];
    const float* h       = (const float*)d_in[1];
    const float* symbols = (const float*)d_in[2];
    const float* gamma   = (const float*)d_in[3];
    const float* beta    = (const float*)d_in[4];
    float* out = (float*)d_out;

    const int B = in_sizes[0] / (NS * ND);
    const int nx = B * NS * ND;

    cudaFuncSetAttribute(gemm_kernel,
                         cudaFuncAttributeMaxDynamicSharedMemorySize, GEMM_SMEM);

    const int xblocks = (nx / 4 + 255) / 256;
    prep_kernel<<<5 + GT_BLOCKS + xblocks, 256>>>(h, symbols, gamma, beta,
                                                  values, nx);

    for (int c0 = 0; c0 < B; c0 += CHUNK) {
        const int nb = min(CHUNK, B - c0);
        dim3 ggrid((nb + 127) / 128, NV / 128, NS);
        gemm_kernel<<<ggrid, 256, GEMM_SMEM>>>(c0, B);
        epi_kernel<<<nb, 256>>>(gamma, beta, out, c0);
    }
}

// round 17
// speedup vs baseline: 1.0685x; 1.0685x over previous
#include <cuda_runtime.h>
#include <cuda_bf16.h>

// Problem constants
#define NS 5
#define ND 64
#define NV 1024
#define NH 961
#define HPITCH 1092
#define BPITCH 1088
#define MAXB 4096
#define CHUNK 2048
#define GT_BLOCKS 320      // NS*NV*ND/4/256
#define GEMM_SMEM 55296    // sBhi 18432 + sBlo 18432 + sXhi 9216 + sXlo 9216

// Precomputed once per launch:
__device__ float g_sp[NS][NV];
// Split-bf16 operands for the conv GEMM: GT[s][o][d] = hp[s][d + 1023 - o]
__device__ __align__(16) __nv_bfloat16 g_GThi[NS][NV][ND];
__device__ __align__(16) __nv_bfloat16 g_GTlo[NS][NV][ND];
__device__ __align__(16) __nv_bfloat16 g_Xhi[MAXB * NS * ND];
__device__ __align__(16) __nv_bfloat16 g_Xlo[MAXB * NS * ND];
__device__ float g_Y[(size_t)MAXB * NS * NV];   // silu(conv) -- pre-activated

__device__ __forceinline__ float silu_f(float y) {
    return y * (1.0f / (1.0f + __expf(-y)));
}
__device__ __forceinline__ float silu_t(float x) {        // tanh.approx, 1 MUFU
    const float h = 0.5f * x;
    float t;
    asm("tanh.approx.f32 %0, %1;" : "=f"(t) : "f"(h));
    return fmaf(h, t, h);
}
__device__ __forceinline__ float warp_sum(float v) {
#pragma unroll
    for (int o = 16; o; o >>= 1) v += __shfl_xor_sync(0xffffffffu, v, o);
    return v;
}
__device__ __forceinline__ void ffma2(unsigned long long& acc,
                                      unsigned long long x,
                                      unsigned long long g) {
    asm("fma.rn.f32x2 %0, %1, %2, %0;" : "+l"(acc) : "l"(x), "l"(g));
}
__device__ __forceinline__ unsigned long long add2(unsigned long long a,
                                                   unsigned long long b) {
    unsigned long long r;
    asm("add.rn.f32x2 %0, %1, %2;" : "=l"(r) : "l"(a), "l"(b));
    return r;
}
__device__ __forceinline__ unsigned long long mul2(unsigned long long a,
                                                   unsigned long long b) {
    unsigned long long r;
    asm("mul.rn.f32x2 %0, %1, %2;" : "=l"(r) : "l"(a), "l"(b));
    return r;
}
__device__ __forceinline__ unsigned long long packf2(float lo, float hi) {
    unsigned long long r;
    asm("mov.b64 %0, {%1, %2};" : "=l"(r) : "r"(__float_as_uint(lo)),
        "r"(__float_as_uint(hi)));
    return r;
}
__device__ __forceinline__ float u64lo(unsigned long long u) {
    return __uint_as_float((unsigned)u);
}
__device__ __forceinline__ float u64hi(unsigned long long u) {
    return __uint_as_float((unsigned)(u >> 32));
}

// m16n8k16 row.col bf16 MMA, fp32 accumulate (D == C).
__device__ __forceinline__ void mma16816(float* c, const unsigned* a,
                                         const unsigned* b) {
    asm volatile(
        "mma.sync.aligned.m16n8k16.row.col.f32.bf16.bf16.f32 "
        "{%0,%1,%2,%3}, {%4,%5,%6,%7}, {%8,%9}, {%0,%1,%2,%3};\n"
        : "+f"(c[0]), "+f"(c[1]), "+f"(c[2]), "+f"(c[3])
        : "r"(a[0]), "r"(a[1]), "r"(a[2]), "r"(a[3]), "r"(b[0]), "r"(b[1]));
}
__device__ __forceinline__ void ldsm4(unsigned* r, const void* p) {
    const unsigned addr = (unsigned)__cvta_generic_to_shared(p);
    asm volatile("ldmatrix.sync.aligned.m8n8.x4.shared.b16 {%0,%1,%2,%3}, [%4];"
                 : "=r"(r[0]), "=r"(r[1]), "=r"(r[2]), "=r"(r[3]) : "r"(addr));
}
__device__ __forceinline__ void cp16(void* dst, const void* src) {
    const unsigned d = (unsigned)__cvta_generic_to_shared(dst);
    asm volatile("cp.async.ca.shared.global [%0], [%1], 16;"
                 :: "r"(d), "l"(src));
}

// ---- fully packed scalar conv (sp branch only; exact fp32) ----
__device__ __forceinline__ void conv4p(const float* __restrict__ gA,
                                       const float* __restrict__ gB,
                                       const float* __restrict__ xs,
                                       float a[4]) {
    const ulonglong2* a2v = (const ulonglong2*)gA;
    const ulonglong2* b2v = (const ulonglong2*)gB;
    const ulonglong2* x2v = (const ulonglong2*)xs;
    unsigned long long A3 = 0ull, A2 = 0ull, A1 = 0ull, A0 = 0ull;
    ulonglong2 GA = a2v[0];
    ulonglong2 GB = b2v[0];
#pragma unroll
    for (int m = 0; m < 16; m++) {
        const ulonglong2 GAn = a2v[m + 1];
        const ulonglong2 GBn = b2v[m + 1];
        const ulonglong2 X = x2v[m];
        ffma2(A3, X.x, GA.x);
        ffma2(A1, X.x, GA.y);
        ffma2(A2, X.x, GB.x);
        ffma2(A0, X.x, GB.y);
        ffma2(A3, X.y, GA.y);
        ffma2(A1, X.y, GAn.x);
        ffma2(A2, X.y, GB.y);
        ffma2(A0, X.y, GBn.x);
        GA = GAn;
        GB = GBn;
    }
    a[3] = u64lo(A3) + u64hi(A3);
    a[2] = u64lo(A2) + u64hi(A2);
    a[1] = u64lo(A1) + u64hi(A1);
    a[0] = u64lo(A0) + u64hi(A0);
}

// --------------------------------------------------------------------------
// Kernel 1: merged prep (sp | GT build | x split), one launch.
// --------------------------------------------------------------------------
__global__ __launch_bounds__(256) void prep_kernel(
    const float* __restrict__ h, const float* __restrict__ symbols,
    const float* __restrict__ gamma, const float* __restrict__ beta,
    const float* __restrict__ values, int n) {
    const int bx = blockIdx.x;
    const int t = threadIdx.x;

    if (bx >= 5 + GT_BLOCKS) {               // ---- x split ----
        const int i = ((bx - 5 - GT_BLOCKS) * 256 + t) * 4;
        if (i < n) {
            const float4 v = *(const float4*)(values + i);
            __nv_bfloat16 h0 = __float2bfloat16(v.x);
            __nv_bfloat16 h1 = __float2bfloat16(v.y);
            __nv_bfloat16 h2 = __float2bfloat16(v.z);
            __nv_bfloat16 h3 = __float2bfloat16(v.w);
            __nv_bfloat162* ph = (__nv_bfloat162*)(&g_Xhi[i]);
            ph[0] = __nv_bfloat162(h0, h1);
            ph[1] = __nv_bfloat162(h2, h3);
            __nv_bfloat162* pl = (__nv_bfloat162*)(&g_Xlo[i]);
            pl[0] = __nv_bfloat162(__float2bfloat16(v.x - __bfloat162float(h0)),
                                   __float2bfloat16(v.y - __bfloat162float(h1)));
            pl[1] = __nv_bfloat162(__float2bfloat16(v.z - __bfloat162float(h2)),
                                   __float2bfloat16(v.w - __bfloat162float(h3)));
        }
        return;
    }
    if (bx >= 5) {                           // ---- GT build ----
        const int idx = (bx - 5) * 256 + t;
#pragma unroll
        for (int q = 0; q < 4; q++) {
            const int e = idx * 4 + q;
            const int s = e / (NV * ND);
            const int rem = e - s * (NV * ND);
            const int o = rem >> 6, d = rem & 63;
            const int j = d + 1023 - o;
            const float v = (j >= 63 && j < 63 + NH) ? h[s * NH + (j - 63)] : 0.f;
            const __nv_bfloat16 hi = __float2bfloat16(v);
            (&g_GThi[0][0][0])[e] = hi;
            (&g_GTlo[0][0][0])[e] = __float2bfloat16(v - __bfloat162float(hi));
        }
        return;
    }

    // ---- sp: conv-net on symbols, one block per s ----
    __shared__ __align__(16) float hpA[HPITCH];
    __shared__ __align__(16) float hpB[BPITCH];
    __shared__ __align__(16) float xs[ND];
    __shared__ float wsum[8], wsq[8], mu_rs[2];
    const int s = bx;
    const int warp = t >> 5, lane = t & 31;

    for (int i = t; i < HPITCH; i += 256)
        hpA[i] = (i >= 63 && i < 63 + NH) ? h[s * NH + (i - 63)] : 0.f;
    for (int i = t; i < BPITCH; i += 256) {
        const int j = i + 1;
        hpB[i] = (j >= 63 && j < 63 + NH) ? h[s * NH + (j - 63)] : 0.f;
    }
    if (t < ND) xs[t] = symbols[s * ND + t];
    __syncthreads();

    const int o0 = 4 * t;
    float a[4];
    conv4p(hpA + (1020 - o0), hpB + (1020 - o0), xs, a);

    float sm = 0.f, sq = 0.f;
#pragma unroll
    for (int k = 0; k < 4; k++) {
        a[k] = silu_f(a[k]);
        sm += a[k];
        sq += a[k] * a[k];
    }
    sm = warp_sum(sm);
    sq = warp_sum(sq);
    if (lane == 0) { wsum[warp] = sm; wsq[warp] = sq; }
    __syncthreads();
    if (t == 0) {
        float s1 = 0.f, s2 = 0.f;
#pragma unroll
        for (int w = 0; w < 8; w++) { s1 += wsum[w]; s2 += wsq[w]; }
        const float mu = s1 * (1.f / NV);
        mu_rs[0] = mu;
        mu_rs[1] = rsqrtf(s2 * (1.f / NV) - mu * mu + 1e-3f);
    }
    __syncthreads();
    const float mu = mu_rs[0], rstd = mu_rs[1];
#pragma unroll
    for (int k = 0; k < 4; k++) {
        const int o = o0 + k;
        g_sp[s][o] = (a[k] - mu) * rstd * gamma[o] + beta[o];
    }
}

// --------------------------------------------------------------------------
// Kernel 2: conv GEMM over one batch chunk + fused silu (round-15 config).
// CTA tile M=64 x N=128 x K=64, 256 threads (8 warps = 2m x 4n),
// warp tile 32x32 -> LDSM/MMA = 0.33. Dynamic SMEM (55.3KB), 3 CTAs/SM.
// --------------------------------------------------------------------------
__global__ __launch_bounds__(256, 3) void gemm_kernel(int c0, int B) {
    extern __shared__ __align__(16) char dsm[];
    __nv_bfloat16 (*sBhi)[72] = (__nv_bfloat16(*)[72])(dsm);           // 128 rows
    __nv_bfloat16 (*sBlo)[72] = (__nv_bfloat16(*)[72])(dsm + 18432);   // 128 rows
    __nv_bfloat16 (*sXhi)[72] = (__nv_bfloat16(*)[72])(dsm + 36864);   //  64 rows
    __nv_bfloat16 (*sXlo)[72] = (__nv_bfloat16(*)[72])(dsm + 46080);   //  64 rows

    const int s = blockIdx.z;
    const int n0 = blockIdx.y * 128;
    const int bm0 = c0 + blockIdx.x * 64;
    const int t = threadIdx.x;

    {   // stage tiles with cp.async
        const uint4* GThi4 = (const uint4*)(&g_GThi[s][0][0]);
        const uint4* GTlo4 = (const uint4*)(&g_GTlo[s][0][0]);
        const uint4* Xhi4 = (const uint4*)g_Xhi;
        const uint4* Xlo4 = (const uint4*)g_Xlo;
#pragma unroll
        for (int u = 0; u < 4; u++) {            // B: 1024 uint4 per array
            const int idx = t + u * 256;
            const int row = idx >> 3, q = idx & 7;
            cp16(&sBhi[row][q * 8], &GThi4[(n0 + row) * 8 + q]);
            cp16(&sBlo[row][q * 8], &GTlo4[(n0 + row) * 8 + q]);
        }
#pragma unroll
        for (int u = 0; u < 2; u++) {            // X: 512 uint4 per array
            const int idx = t + u * 256;
            const int row = idx >> 3, q = idx & 7;
            const int r = min(bm0 + row, B - 1);
            cp16(&sXhi[row][q * 8], &Xhi4[(r * NS + s) * 8 + q]);
            cp16(&sXlo[row][q * 8], &Xlo4[(r * NS + s) * 8 + q]);
        }
        asm volatile("cp.async.commit_group;");
        asm volatile("cp.async.wait_group 0;");
    }
    __syncthreads();

    const int warp = t >> 5, lane = t & 31;
    const int wm = warp & 1, wn = warp >> 1;     // wn in 0..3
    const int g = lane >> 2, t4 = lane & 3;

    float acc[2][4][4];
#pragma unroll
    for (int mi = 0; mi < 2; mi++)
#pragma unroll
        for (int j = 0; j < 4; j++)
#pragma unroll
            for (int c = 0; c < 4; c++) acc[mi][j][c] = 0.f;

    const int arow_l = (lane & 15);
    const int acol_l = (lane >> 4) << 3;
    const int brow_l = ((lane >> 4) << 3) + (lane & 7);
    const int bcol_l = ((lane >> 3) & 1) << 3;

#pragma unroll
    for (int ks = 0; ks < 4; ks++) {
        const int k0 = ks * 16;
        unsigned ahi[2][4], alo[2][4], bhi[2][4], blo[2][4];
#pragma unroll
        for (int mi = 0; mi < 2; mi++) {
            const int r = wm * 32 + mi * 16 + arow_l;
            ldsm4(ahi[mi], &sXhi[r][k0 + acol_l]);
            ldsm4(alo[mi], &sXlo[r][k0 + acol_l]);
        }
#pragma unroll
        for (int half = 0; half < 2; half++) {
            const int nr = wn * 32 + half * 16 + brow_l;
            ldsm4(bhi[half], &sBhi[nr][k0 + bcol_l]);
            ldsm4(blo[half], &sBlo[nr][k0 + bcol_l]);
        }
#pragma unroll
        for (int j = 0; j < 4; j++) {
            const int hf = j >> 1, sub = j & 1;
            const unsigned bh[2] = {bhi[hf][2 * sub], bhi[hf][2 * sub + 1]};
            const unsigned bl[2] = {blo[hf][2 * sub], blo[hf][2 * sub + 1]};
#pragma unroll
            for (int mi = 0; mi < 2; mi++) {
                mma16816(acc[mi][j], ahi[mi], bh);
                mma16816(acc[mi][j], ahi[mi], bl);
                mma16816(acc[mi][j], alo[mi], bh);
            }
        }
    }

    // silu + store Y
#pragma unroll
    for (int mi = 0; mi < 2; mi++) {
        const int r0 = bm0 + wm * 32 + mi * 16 + g;
#pragma unroll
        for (int j = 0; j < 4; j++) {
            const int col = n0 + wn * 32 + j * 8 + 2 * t4;
            if (r0 < B)
                *(float2*)(g_Y + ((size_t)r0 * NS + s) * NV + col) =
                    make_float2(silu_f(acc[mi][j][0]), silu_f(acc[mi][j][1]));
            if (r0 + 8 < B)
                *(float2*)(g_Y + ((size_t)(r0 + 8) * NS + s) * NV + col) =
                    make_float2(silu_f(acc[mi][j][2]), silu_f(acc[mi][j][3]));
        }
    }
}

// --------------------------------------------------------------------------
// Kernel 3: epilogue for one chunk. One CTA per batch. Y is pre-silu'd.
// --------------------------------------------------------------------------
__global__ __launch_bounds__(256, 4) void epi_kernel(
    const float* __restrict__ gamma, const float* __restrict__ beta,
    float* __restrict__ out, int c0) {
    __shared__ float wsum[NS][8], wsq[NS][8];
    __shared__ float mu_s[NS], rs_s[NS];
    __shared__ unsigned spartP[NS][2][8];
    __shared__ float score[25];
    __shared__ float prob[NS][NS];

    const int b = c0 + blockIdx.x;
    const int t = threadIdx.x;
    const int warp = t >> 5, lane = t & 31;

    float4 VPX[NS];
#pragma unroll
    for (int i = 0; i < NS; i++) {
        const float4 v = ((const float4*)(g_Y + ((size_t)b * NS + i) * NV))[t];
        VPX[i] = v;
        float sm = v.x + v.y + v.z + v.w;
        float sq = v.x * v.x + v.y * v.y + v.z * v.z + v.w * v.w;
        sm = warp_sum(sm);
        sq = warp_sum(sq);
        if (lane == 0) { wsum[i][warp] = sm; wsq[i][warp] = sq; }
    }
    __syncthreads();
    if (t < NS) {
        float s1 = 0.f, s2 = 0.f;
#pragma unroll
        for (int w = 0; w < 8; w++) { s1 += wsum[t][w]; s2 += wsq[t][w]; }
        const float mu = s1 * (1.f / NV);
        mu_s[t] = mu;
        rs_s[t] = rsqrtf(s2 * (1.f / NV) - mu * mu + 1e-3f);
    }
    __syncthreads();

    const float4 gm4 = ((const float4*)gamma)[t];
    const float4 bt4 = ((const float4*)beta)[t];
    unsigned long long VU[NS][2];
#pragma unroll
    for (int i = 0; i < NS; i++) {
        const float mu = mu_s[i], rs = rs_s[i];
        VU[i][0] = packf2((VPX[i].x - mu) * rs * gm4.x + bt4.x,
                          (VPX[i].y - mu) * rs * gm4.y + bt4.y);
        VU[i][1] = packf2((VPX[i].z - mu) * rs * gm4.z + bt4.z,
                          (VPX[i].w - mu) * rs * gm4.w + bt4.w);
    }

    unsigned long long SU[NS][2];
#pragma unroll
    for (int j = 0; j < NS; j++) {
        const float4 sp = ((const float4*)(&g_sp[j][0]))[t];
        SU[j][0] = packf2(sp.x, sp.y);
        SU[j][1] = packf2(sp.z, sp.w);
    }

#pragma unroll
    for (int j = 0; j < NS; j++) {
        unsigned p0 = 0, p1 = 0;
#pragma unroll
        for (int i = 0; i < NS; i++) {
            const unsigned long long x0 = VU[i][0] ^ add2(VU[i][0], SU[j][0]);
            const unsigned long long x1 = VU[i][1] ^ add2(VU[i][1], SU[j][1]);
            const unsigned a = (unsigned)((x0 >> 31) & 1u) + (unsigned)(x0 >> 63) +
                               (unsigned)((x1 >> 31) & 1u) + (unsigned)(x1 >> 63);
            if (i < 4) p0 += a << (8 * i); else p1 = a;
        }
        p0 = __reduce_add_sync(0xffffffffu, p0);
        p1 = __reduce_add_sync(0xffffffffu, p1);
        if (lane == 0) { spartP[j][0][warp] = p0; spartP[j][1][warp] = p1; }
    }
    __syncthreads();
    if (t < 25) {
        const int j = t / 5, i = t % 5;
        unsigned sm = 0;
#pragma unroll
        for (int w = 0; w < 8; w++)
            sm += (i < 4) ? ((spartP[j][0][w] >> (8 * i)) & 255u)
                          : (spartP[j][1][w] & 255u);
        score[t] = (float)(NV - 2 * (int)sm) * (1.f / NV);
    }
    __syncthreads();
    if (t < NS) {
        float sc[NS];
        float ssum = 0.f;
#pragma unroll
        for (int i = 0; i < NS; i++) {
            sc[i] = __expf(score[t * NS + i]);
            ssum += sc[i];
        }
        const float inv = 1.f / ssum;
#pragma unroll
        for (int i = 0; i < NS; i++) prob[t][i] = sc[i] * inv;
    }
    __syncthreads();

    float4* out4 = (float4*)(out + (size_t)b * (NS * NV));
#pragma unroll
    for (int j = 0; j < NS; j++) {
        unsigned long long at0 = 0ull, at1 = 0ull;
#pragma unroll
        for (int i = 0; i < NS; i++) {
            const float p = prob[j][i];
            const unsigned long long pp = packf2(p, p);
            ffma2(at0, pp, VU[i][0]);
            ffma2(at1, pp, VU[i][1]);
        }
        at0 = mul2(at0, SU[j][0]);
        at1 = mul2(at1, SU[j][1]);
        float4 w4;
        w4.x = silu_t(u64lo(at0));
        w4.y = silu_t(u64hi(at0));
        w4.z = silu_t(u64lo(at1));
        w4.w = silu_t(u64hi(at1));
        out4[j * 256 + t] = w4;
    }
}

extern "C" void kernel_launch(void* const* d_in, const int* in_sizes, int n_in,
                              void* d_out, int out_size) {
    const float* values  = (const float*)d_in[0];
    const float* h       = (const float*)d_in[1];
    const float* symbols = (const float*)d_in[2];
    const float* gamma   = (const float*)d_in[3];
    const float* beta    = (const float*)d_in[4];
    float* out = (float*)d_out;

    const int B = in_sizes[0] / (NS * ND);
    const int nx = B * NS * ND;

    // Host-side resources created once (host objects, not device memory).
    static cudaStream_t sB = nullptr;
    static cudaEvent_t evFork = nullptr, evJoin = nullptr;
    if (sB == nullptr) {
        cudaStreamCreateWithFlags(&sB, cudaStreamNonBlocking);
        cudaEventCreateWithFlags(&evFork, cudaEventDisableTiming);
        cudaEventCreateWithFlags(&evJoin, cudaEventDisableTiming);
    }

    cudaFuncSetAttribute(gemm_kernel,
                         cudaFuncAttributeMaxDynamicSharedMemorySize, GEMM_SMEM);

    const int xblocks = (nx / 4 + 255) / 256;
    prep_kernel<<<5 + GT_BLOCKS + xblocks, 256>>>(h, symbols, gamma, beta,
                                                  values, nx);

    if (B <= CHUNK) {
        dim3 ggrid((B + 63) / 64, NV / 128, NS);
        gemm_kernel<<<ggrid, 256, GEMM_SMEM>>>(0, B);
        epi_kernel<<<B, 256>>>(gamma, beta, out, 0);
        return;
    }

    // Two chunks (B <= 2*CHUNK): overlap epi(c0) with gemm(c1) via
    // fork-join streams (graph-capturable pattern).
    const int nb0 = CHUNK;
    const int nb1 = B - CHUNK;

    dim3 g0((nb0 + 63) / 64, NV / 128, NS);
    gemm_kernel<<<g0, 256, GEMM_SMEM>>>(0, B);
    cudaEventRecord(evFork, 0);

    cudaStreamWaitEvent(sB, evFork, 0);
    dim3 g1((nb1 + 63) / 64, NV / 128, NS);
    gemm_kernel<<<g1, 256, GEMM_SMEM, sB>>>(CHUNK, B);
    cudaEventRecord(evJoin, sB);

    epi_kernel<<<nb0, 256>>>(gamma, beta, out, 0);       // overlaps gemm(c1)

    cudaStreamWaitEvent(0, evJoin, 0);
    epi_kernel<<<nb1, 256>>>(gamma, beta, out, CHUNK);
}